// round 17
// baseline (speedup 1.0000x reference)
#include <cuda_runtime.h>
#include <cuda_fp16.h>
#include <math_constants.h>

#define NN    20000
#define TT    4
#define EE    320000
#define INF_  32
#define HF    16
#define OUTF  16
#define HEADS 8
#define C1    (HEADS * HF)   // 128
#define SLOPE 0.2f
#define SLOTS 96

#define BUCKET_BLOCKS 313    // ceil(EE/4/256)
#define FUSED1_BLOCKS 1250   // (NN*TT/8)/8

// feat1 fp16 layout (split-half, per src node sn):
//   half2 index = sn*256 + half*128 + (t*8+h)*4 + pairIdx
// uint4 index  = sn*64  + half*32  + t*8 + h
__device__ __half2 g_feat1h[NN * TT * 64];
__device__ float   g_el1[NN * TT * HEADS];   // idx = sn*32 + t*8 + h
__device__ float   g_er1[NN * TT * HEADS];
__device__ __half2 g_feat2h[NN * TT * 8];
__device__ float   g_el2[NN * TT];
__device__ float   g_er2[NN * TT];
__device__ int     g_deg[NN];                // zero-init at load; re-zeroed by k_agg2
__device__ int     g_esrc[NN * SLOTS];       // src*TT per incoming edge

// ---------------- merged build: bucket scatter + layer-1 feat/el/er --------
__global__ void k_build(const int* __restrict__ dst, const int* __restrict__ src,
                        const float* __restrict__ x,
                        const float* __restrict__ W1,
                        const float* __restrict__ al1,
                        const float* __restrict__ ar1) {
    if (blockIdx.x < BUCKET_BLOCKS) {
        int i = (blockIdx.x * blockDim.x + threadIdx.x) * 4;
        if (i + 4 <= EE) {
            int4 d4 = *reinterpret_cast<const int4*>(dst + i);
            int4 s4 = *reinterpret_cast<const int4*>(src + i);
            int p0 = atomicAdd(&g_deg[d4.x], 1);
            int p1 = atomicAdd(&g_deg[d4.y], 1);
            int p2 = atomicAdd(&g_deg[d4.z], 1);
            int p3 = atomicAdd(&g_deg[d4.w], 1);
            if (p0 < SLOTS) g_esrc[d4.x * SLOTS + p0] = s4.x * TT;
            if (p1 < SLOTS) g_esrc[d4.y * SLOTS + p1] = s4.y * TT;
            if (p2 < SLOTS) g_esrc[d4.z * SLOTS + p2] = s4.z * TT;
            if (p3 < SLOTS) g_esrc[d4.w * SLOTS + p3] = s4.w * TT;
        } else {
            for (; i < EE; i++) {
                int d = dst[i];
                int p = atomicAdd(&g_deg[d], 1);
                if (p < SLOTS) g_esrc[d * SLOTS + p] = src[i] * TT;
            }
        }
        return;
    }

    // ---- fused1 path: 8 nt-rows per warp ----
    int warp = ((blockIdx.x - BUCKET_BLOCKS) * blockDim.x + threadIdx.x) >> 5;
    int lane = threadIdx.x & 31;
    int nt0 = warp * 8;
    if (nt0 >= NN * TT) return;

    float xv[8];
#pragma unroll
    for (int rr = 0; rr < 8; rr++)
        xv[rr] = x[(nt0 + rr) * INF_ + lane];

    const float4* W4 = reinterpret_cast<const float4*>(W1);

    float4 acc[8];
#pragma unroll
    for (int rr = 0; rr < 8; rr++) acc[rr] = make_float4(0.f, 0.f, 0.f, 0.f);

#pragma unroll
    for (int k = 0; k < INF_; k++) {
        float4 w = W4[k * 32 + lane];
#pragma unroll
        for (int rr = 0; rr < 8; rr++) {
            float xk = __shfl_sync(0xffffffffu, xv[rr], k);
            acc[rr].x = fmaf(xk, w.x, acc[rr].x);
            acc[rr].y = fmaf(xk, w.y, acc[rr].y);
            acc[rr].z = fmaf(xk, w.z, acc[rr].z);
            acc[rr].w = fmaf(xk, w.w, acc[rr].w);
        }
    }

    float4 a = reinterpret_cast<const float4*>(al1)[lane];
    float4 r = reinterpret_cast<const float4*>(ar1)[lane];
    int h    = lane >> 2;
    int halfBit = (lane >> 1) & 1;
    int pairOff = (lane & 1) * 2;

#pragma unroll
    for (int rr = 0; rr < 8; rr++) {
        int nt = nt0 + rr;
        int sn = nt >> 2, t = nt & 3;
        float4 ac = acc[rr];
        int base = sn * 256 + halfBit * 128 + (t * 8 + h) * 4 + pairOff;
        g_feat1h[base]     = __floats2half2_rn(ac.x, ac.y);
        g_feat1h[base + 1] = __floats2half2_rn(ac.z, ac.w);

        float el = ac.x * a.x + ac.y * a.y + ac.z * a.z + ac.w * a.w;
        float er = ac.x * r.x + ac.y * r.y + ac.z * r.z + ac.w * r.w;
        el += __shfl_xor_sync(0xffffffffu, el, 1);
        el += __shfl_xor_sync(0xffffffffu, el, 2);
        er += __shfl_xor_sync(0xffffffffu, er, 1);
        er += __shfl_xor_sync(0xffffffffu, er, 2);
        if ((lane & 3) == 0) {
            g_el1[nt * HEADS + h] = el;
            g_er1[nt * HEADS + h] = er;
        }
    }
}

// ---------------- merged: layer1 aggregation + layer2 feat/el/er -----------
// Block: 4 dsts, 2 warps per dst (each warp covers 2 t's).
// Lane = [t-in-pair:1][h:3][half:1] -> owns 8 channels = one uint4 feat load.
__global__ void __launch_bounds__(256) k_agg1f2(const float* __restrict__ b1,
                                                const float* __restrict__ W2,
                                                const float* __restrict__ al2,
                                                const float* __restrict__ ar2) {
    __shared__ float sh_h[4 * TT * C1];   // 8 KB: [dstInBlk][t][128]
    __shared__ float sh_W[C1 * OUTF];     // 8 KB
    int tid  = threadIdx.x;
    int w    = tid >> 5;
    int lane = tid & 31;

    const float4* W24 = reinterpret_cast<const float4*>(W2);
    reinterpret_cast<float4*>(sh_W)[tid]       = W24[tid];
    reinterpret_cast<float4*>(sh_W)[tid + 256] = W24[tid + 256];

    // ---------- phase 1 ----------
    {
        int dLocal = w >> 1;
        int d      = blockIdx.x * 4 + dLocal;
        int tp     = w & 1;
        int t      = tp * 2 + (lane >> 4);
        int sub    = lane & 15;
        int h      = sub >> 1;
        int halfb  = sub & 1;
        int eo     = t * 8 + h;                 // el offset within node block
        int fo     = halfb * 32 + eo;           // feat uint4 offset within node block

        int deg = g_deg[d];
        const int* es = g_esrc + d * SLOTS;

        int eb[16];
        *reinterpret_cast<int4*>(eb)      = *reinterpret_cast<const int4*>(es);
        *reinterpret_cast<int4*>(eb + 4)  = *reinterpret_cast<const int4*>(es + 4);
        *reinterpret_cast<int4*>(eb + 8)  = *reinterpret_cast<const int4*>(es + 8);
        *reinterpret_cast<int4*>(eb + 12) = *reinterpret_cast<const int4*>(es + 12);

        float er = g_er1[(d << 5) + eo];
        float s = 0.f;
        float accf[8];
#pragma unroll
        for (int j = 0; j < 8; j++) accf[j] = 0.f;

        const uint4* F = reinterpret_cast<const uint4*>(g_feat1h);

        auto batch4 = [&](int s0, int s1, int s2, int s3) {
            float e0 = g_el1[(s0 << 3) + eo] + er;
            float e1 = g_el1[(s1 << 3) + eo] + er;
            float e2 = g_el1[(s2 << 3) + eo] + er;
            float e3 = g_el1[(s3 << 3) + eo] + er;
            uint4 v0 = F[(s0 << 4) + fo];
            uint4 v1 = F[(s1 << 4) + fo];
            uint4 v2 = F[(s2 << 4) + fo];
            uint4 v3 = F[(s3 << 4) + fo];
            e0 = (e0 > 0.f) ? e0 : SLOPE * e0;
            e1 = (e1 > 0.f) ? e1 : SLOPE * e1;
            e2 = (e2 > 0.f) ? e2 : SLOPE * e2;
            e3 = (e3 > 0.f) ? e3 : SLOPE * e3;
            float w0 = __expf(e0), w1 = __expf(e1);
            float w2 = __expf(e2), w3 = __expf(e3);
            s += (w0 + w1) + (w2 + w3);
            __half2 w0h = __float2half2_rn(w0);
            __half2 w1h = __float2half2_rn(w1);
            __half2 w2h = __float2half2_rn(w2);
            __half2 w3h = __float2half2_rn(w3);
            const __half2* A = reinterpret_cast<const __half2*>(&v0);
            const __half2* B = reinterpret_cast<const __half2*>(&v1);
            const __half2* C = reinterpret_cast<const __half2*>(&v2);
            const __half2* D = reinterpret_cast<const __half2*>(&v3);
#pragma unroll
            for (int j = 0; j < 4; j++) {
                __half2 p = __hmul2(A[j], w0h);
                p = __hfma2(B[j], w1h, p);
                p = __hfma2(C[j], w2h, p);
                p = __hfma2(D[j], w3h, p);
                float2 pf = __half22float2(p);
                accf[2 * j]     += pf.x;
                accf[2 * j + 1] += pf.y;
            }
        };

        int k = 0;
#pragma unroll
        for (int b = 0; b < 4; b++) {
            if (k + 4 <= deg) {
                batch4(eb[4 * b], eb[4 * b + 1], eb[4 * b + 2], eb[4 * b + 3]);
                k += 4;
            }
        }
        for (; k + 4 <= deg; k += 4)
            batch4(es[k], es[k + 1], es[k + 2], es[k + 3]);
        for (; k < deg; k++) {
            int s0 = es[k];
            float e0 = g_el1[(s0 << 3) + eo] + er;
            uint4 v0 = F[(s0 << 4) + fo];
            e0 = (e0 > 0.f) ? e0 : SLOPE * e0;
            float w0 = __expf(e0);
            s += w0;
            const __half2* A = reinterpret_cast<const __half2*>(&v0);
#pragma unroll
            for (int j = 0; j < 4; j++) {
                float2 fa = __half22float2(A[j]);
                accf[2 * j]     += fa.x * w0;
                accf[2 * j + 1] += fa.y * w0;
            }
        }

        float inv = (deg > 0) ? (1.f / s) : 0.f;   // full per-(d,t,h) denominator

        const float4* B4 = reinterpret_cast<const float4*>(b1);
        float4* SH = reinterpret_cast<float4*>(sh_h + (dLocal * TT + t) * C1 + h * 16 + halfb * 8);
#pragma unroll
        for (int q = 0; q < 2; q++) {
            float4 bb = B4[(h << 2) + (halfb << 1) + q];
            float4 o;
            o.x = fmaf(accf[q * 4 + 0], inv, bb.x);
            o.y = fmaf(accf[q * 4 + 1], inv, bb.y);
            o.z = fmaf(accf[q * 4 + 2], inv, bb.z);
            o.w = fmaf(accf[q * 4 + 3], inv, bb.w);
            SH[q] = o;
        }
    }
    __syncthreads();

    // ---------- phase 2: feat2 = h1*W2, el2/er2 (16 rows, one per 16 threads) --
    {
        int c   = tid & 15;
        int row = tid >> 4;                   // 0..15 = dstInBlk*4 + t
        float a2 = al2[c];
        float r2 = ar2[c];
        const float4* hr4 = reinterpret_cast<const float4*>(sh_h + row * C1);
        float acc = 0.f;
#pragma unroll
        for (int j = 0; j < 32; j++) {
            float4 hv = hr4[j];
            int kk = j * 4;
            acc = fmaf(hv.x, sh_W[(kk + 0) * OUTF + c], acc);
            acc = fmaf(hv.y, sh_W[(kk + 1) * OUTF + c], acc);
            acc = fmaf(hv.z, sh_W[(kk + 2) * OUTF + c], acc);
            acc = fmaf(hv.w, sh_W[(kk + 3) * OUTF + c], acc);
        }
        int nt = (blockIdx.x * 4 + (row >> 2)) * TT + (row & 3);

        float hi = __shfl_down_sync(0xffffffffu, acc, 1);
        if ((c & 1) == 0)
            g_feat2h[nt * 8 + (c >> 1)] = __floats2half2_rn(acc, hi);

        float el = acc * a2;
        float er = acc * r2;
        el += __shfl_xor_sync(0xffffffffu, el, 1);
        el += __shfl_xor_sync(0xffffffffu, el, 2);
        el += __shfl_xor_sync(0xffffffffu, el, 4);
        el += __shfl_xor_sync(0xffffffffu, el, 8);
        er += __shfl_xor_sync(0xffffffffu, er, 1);
        er += __shfl_xor_sync(0xffffffffu, er, 2);
        er += __shfl_xor_sync(0xffffffffu, er, 4);
        er += __shfl_xor_sync(0xffffffffu, er, 8);
        if (c == 0) {
            g_el2[nt] = el;
            g_er2[nt] = er;
        }
    }
}

// ---------------- layer 2 aggregation: warp per dst, half2 batches ---------
// Also re-zeroes g_deg[d] so the next invocation starts clean (no memset).
__global__ void k_agg2(const float* __restrict__ b2, float* __restrict__ out) {
    int warp = (blockIdx.x * blockDim.x + threadIdx.x) >> 5;
    int lane = threadIdx.x & 31;
    if (warp >= NN) return;
    int d  = warp;
    int t  = lane >> 3;
    int cp = lane & 7;

    int deg = g_deg[d];
    const int* es = g_esrc + d * SLOTS;
    int dt = d * TT + t;

    int eb[16];
    *reinterpret_cast<int4*>(eb)      = *reinterpret_cast<const int4*>(es);
    *reinterpret_cast<int4*>(eb + 4)  = *reinterpret_cast<const int4*>(es + 4);
    *reinterpret_cast<int4*>(eb + 8)  = *reinterpret_cast<const int4*>(es + 8);
    *reinterpret_cast<int4*>(eb + 12) = *reinterpret_cast<const int4*>(es + 12);

    float er = g_er2[dt];
    float s = 0.f;
    float2 acc = make_float2(0.f, 0.f);

    auto batch4 = [&](int b0, int b1i, int b2i, int b3) {
        int a0 = b0 + t, a1 = b1i + t, a2 = b2i + t, a3 = b3 + t;
        float e0 = g_el2[a0] + er;
        float e1 = g_el2[a1] + er;
        float e2 = g_el2[a2] + er;
        float e3 = g_el2[a3] + er;
        __half2 v0 = g_feat2h[(a0 << 3) + cp];
        __half2 v1 = g_feat2h[(a1 << 3) + cp];
        __half2 v2 = g_feat2h[(a2 << 3) + cp];
        __half2 v3 = g_feat2h[(a3 << 3) + cp];
        e0 = (e0 > 0.f) ? e0 : SLOPE * e0;
        e1 = (e1 > 0.f) ? e1 : SLOPE * e1;
        e2 = (e2 > 0.f) ? e2 : SLOPE * e2;
        e3 = (e3 > 0.f) ? e3 : SLOPE * e3;
        float w0 = __expf(e0), w1 = __expf(e1);
        float w2 = __expf(e2), w3 = __expf(e3);
        s += (w0 + w1) + (w2 + w3);
        __half2 p = __hmul2(v0, __float2half2_rn(w0));
        p = __hfma2(v1, __float2half2_rn(w1), p);
        p = __hfma2(v2, __float2half2_rn(w2), p);
        p = __hfma2(v3, __float2half2_rn(w3), p);
        float2 pf = __half22float2(p);
        acc.x += pf.x;
        acc.y += pf.y;
    };

    int k = 0;
#pragma unroll
    for (int b = 0; b < 4; b++) {
        if (k + 4 <= deg) {
            batch4(eb[4 * b], eb[4 * b + 1], eb[4 * b + 2], eb[4 * b + 3]);
            k += 4;
        }
    }
    for (; k + 4 <= deg; k += 4)
        batch4(es[k], es[k + 1], es[k + 2], es[k + 3]);
    for (; k < deg; k++) {
        int a0 = es[k] + t;
        float e0 = g_el2[a0] + er;
        __half2 v0 = g_feat2h[(a0 << 3) + cp];
        e0 = (e0 > 0.f) ? e0 : SLOPE * e0;
        float w0 = __expf(e0);
        s += w0;
        float2 f0 = __half22float2(v0);
        acc.x = fmaf(f0.x, w0, acc.x);
        acc.y = fmaf(f0.y, w0, acc.y);
    }

    float inv = (deg > 0) ? (1.f / s) : 0.f;
    float2 bb = reinterpret_cast<const float2*>(b2)[cp];
    float2 o;
    o.x = fmaf(acc.x, inv, bb.x);
    o.y = fmaf(acc.y, inv, bb.y);
    reinterpret_cast<float2*>(out)[(dt << 3) + cp] = o;

    if (lane == 0) g_deg[d] = 0;   // leave state clean for next invocation
}

// ---------------- launch ----------------------------------------------------
extern "C" void kernel_launch(void* const* d_in, const int* in_sizes, int n_in,
                              void* d_out, int out_size) {
    const float* x   = (const float*)d_in[0];
    const int*   src = (const int*)d_in[1];
    const int*   dst = (const int*)d_in[2];
    const float* W1  = (const float*)d_in[3];
    const float* al1 = (const float*)d_in[4];
    const float* ar1 = (const float*)d_in[5];
    const float* b1  = (const float*)d_in[6];
    const float* W2  = (const float*)d_in[7];
    const float* al2 = (const float*)d_in[8];
    const float* ar2 = (const float*)d_in[9];
    const float* b2  = (const float*)d_in[10];
    float* out = (float*)d_out;

    const int TB = 256;

    k_build<<<BUCKET_BLOCKS + FUSED1_BLOCKS, TB>>>(dst, src, x, W1, al1, ar1);
    k_agg1f2<<<NN / 4, TB>>>(b1, W2, al2, ar2);
    k_agg2<<<(NN + 7) / 8, TB>>>(b2, out);
}